// round 4
// baseline (speedup 1.0000x reference)
#include <cuda_runtime.h>
#include <math.h>

// ---------------------------------------------------------------------------
// LSTM autoencoder: B=64, T=512, F=256, H=1024
//   init -> gemm(Xe) -> persistent encoder scan -> gemm(Xd)
//        -> persistent decoder scan -> gemm(out)       (6 graph nodes)
// R4: scan inner loop uses fma.rn.f32x2 (packed fp32 FMA, 2x FFMA issue rate),
//     gate-interleaved weights so activations are register-resident, c state
//     lives in registers across all 512 steps, 1 sync per k-chunk.
// ---------------------------------------------------------------------------

#define TSTEPS 512
#define BATCH  64
#define FDIM   256
#define HDIM   1024
#define G4     4096
#define NCTA_SCAN 128

#define HSTR   130          // duplicated-h smem row stride (floats)
#define HBUFSZ (32 * HSTR)  // one 32-k chunk buffer

// Scratch in device globals (no allocation allowed).
__device__ float g_Xe  [134217728]; // [512][64][4096]
__device__ float g_Xd  [134217728]; // [512][64][4096]
__device__ float g_ench[33554432];  // [512][64][1024]
__device__ float g_dech[33554432];  // [512][64][1024]
__device__ float g_c   [BATCH * HDIM];
__device__ float g_h0  [BATCH * HDIM];
__device__ unsigned g_bar_gen;
__device__ unsigned g_bar_cnt;

__global__ void init_state_kernel() {
    int i = blockIdx.x * blockDim.x + threadIdx.x;
    if (i < BATCH * HDIM) { g_c[i] = 0.0f; g_h0[i] = 0.0f; }
    if (i == 0) { g_bar_gen = 0u; g_bar_cnt = 0u; }
}

// packed fp32x2 FMA: acc = a*b + acc (lanewise on 2 floats in a 64-bit reg)
#define FMA_F32X2(acc, a, b) \
    asm("fma.rn.f32x2 %0, %1, %2, %0;" : "+l"(acc) : "l"(a), "l"(b))
#define UNPACK_F32X2(lo, hi, in) \
    asm("mov.b64 {%0, %1}, %2;" : "=f"(lo), "=f"(hi) : "l"(in))

// Sense-reversal grid barrier across the 128 co-resident scan CTAs.
__device__ __forceinline__ void grid_barrier() {
    __syncthreads();
    if (threadIdx.x == 0) {
        unsigned e = *(volatile unsigned*)&g_bar_gen;
        __threadfence();                       // release my CTA's writes
        unsigned a = atomicAdd(&g_bar_cnt, 1u);
        if (a == NCTA_SCAN - 1) {
            atomicExch(&g_bar_cnt, 0u);
            __threadfence();
            *(volatile unsigned*)&g_bar_gen = e + 1u;
        } else {
            while (*(volatile unsigned*)&g_bar_gen == e) { }
            __threadfence();                   // acquire
        }
    }
    __syncthreads();
}

__device__ __forceinline__ float sigmoidf_fast(float x) {
    return 1.0f / (1.0f + __expf(-x));
}

// ---------------------------------------------------------------------------
// fp32 GEMM + bias (unchanged from R3: total gemm time ~35us, not the lever).
// ---------------------------------------------------------------------------
__global__ void __launch_bounds__(256) gemm128_kernel(
    const float* __restrict__ A, const float* __restrict__ W,
    const float* __restrict__ bias, float* __restrict__ C,
    int K, int a_sb, int a_st, int c_sb, int c_st)
{
    __shared__ __align__(16) float As[8][132];
    __shared__ __align__(16) float Bs[8][132];

    const int m0t = blockIdx.y * 128;
    const int n0t = blockIdx.x * 128;
    const int tid = threadIdx.x;
    const int lm  = tid >> 1;
    const int lk  = (tid & 1) * 4;
    const int mb  = (tid >> 4) * 8;
    const int nb  = (tid & 15) * 8;

    const int am = m0t + lm;
    const size_t aoff = (size_t)(am & 63) * a_sb + (size_t)(am >> 6) * a_st;
    const float* arow = A + aoff + lk;
    const float* wrow = W + (size_t)(n0t + lm) * K + lk;

    float acc[8][8] = {};
    float4 av = *(const float4*)(arow);
    float4 bv = *(const float4*)(wrow);

    const int nchunks = K >> 3;
    for (int ch = 0; ch < nchunks; ch++) {
        __syncthreads();
        As[lk + 0][lm] = av.x; As[lk + 1][lm] = av.y;
        As[lk + 2][lm] = av.z; As[lk + 3][lm] = av.w;
        Bs[lk + 0][lm] = bv.x; Bs[lk + 1][lm] = bv.y;
        Bs[lk + 2][lm] = bv.z; Bs[lk + 3][lm] = bv.w;
        __syncthreads();
        if (ch + 1 < nchunks) {
            av = *(const float4*)(arow + (ch + 1) * 8);
            bv = *(const float4*)(wrow + (ch + 1) * 8);
        }
#pragma unroll
        for (int q = 0; q < 8; q++) {
            float4 a0 = *(const float4*)&As[q][mb];
            float4 a1 = *(const float4*)&As[q][mb + 4];
            float4 b0 = *(const float4*)&Bs[q][nb];
            float4 b1 = *(const float4*)&Bs[q][nb + 4];
            float ar[8] = {a0.x, a0.y, a0.z, a0.w, a1.x, a1.y, a1.z, a1.w};
            float br[8] = {b0.x, b0.y, b0.z, b0.w, b1.x, b1.y, b1.z, b1.w};
#pragma unroll
            for (int r = 0; r < 8; r++)
#pragma unroll
                for (int c = 0; c < 8; c++)
                    acc[r][c] += ar[r] * br[c];
        }
    }

    float4 bi0 = *(const float4*)(bias + n0t + nb);
    float4 bi1 = *(const float4*)(bias + n0t + nb + 4);
    const float bb[8] = {bi0.x, bi0.y, bi0.z, bi0.w, bi1.x, bi1.y, bi1.z, bi1.w};

#pragma unroll
    for (int r = 0; r < 8; r++) {
        int m = m0t + mb + r;
        size_t cbase = (size_t)(m & 63) * c_sb + (size_t)(m >> 6) * c_st
                     + n0t + nb;
        float4 o0 = make_float4(acc[r][0] + bb[0], acc[r][1] + bb[1],
                                acc[r][2] + bb[2], acc[r][3] + bb[3]);
        float4 o1 = make_float4(acc[r][4] + bb[4], acc[r][5] + bb[5],
                                acc[r][6] + bb[6], acc[r][7] + bb[7]);
        *(float4*)(C + cbase)     = o0;
        *(float4*)(C + cbase + 4) = o1;
    }
}

// ---------------------------------------------------------------------------
// Persistent LSTM scan, f32x2 edition.
// CTA j (0..127) owns h columns [j*8, j*8+8).
// Thread (tid): rows m0 = (tid>>3)*2 .. +1 ; h-col cj = tid&7.
// It computes the (i,f,g,o) gate quadruple for (row, jc0+cj), accumulated as
// two f32x2 pairs per row: (i,f) and (g,o).
// Whh slice pre-interleaved in smem: Ws[k*36 + cj*4 + gate].
// h chunks staged DUPLICATED in smem: Hd[kc*130 + 2m] = (h, h) so the f32x2
// broadcast operand is one LDS.64, no packing movs in the inner loop.
// Cell state c lives in registers for the whole 512-step scan.
// smem: Ws 147456B + 2 x 32x130 dup-h = 180736B -> 1 CTA/SM.
// ---------------------------------------------------------------------------
__global__ void __launch_bounds__(256) lstm_scan_kernel(
    const float* __restrict__ Hin0,     // [64][1024] initial h
    const float* __restrict__ Xp_base,  // [512][64][4096] input-part (+bias)
    const float* __restrict__ Whh,      // [4096][1024]
    float* __restrict__ cbuf,           // [64][1024] c in/out (seed/handoff)
    float* __restrict__ Hser)           // [512][64][1024] per-step h out
{
    extern __shared__ float sm[];
    float* Ws = sm;                 // [1024][36], col index c = cj*4 + gate
    float* Hd = sm + 36864;         // 2 x HBUFSZ duplicated-h chunk buffers

    const int j   = blockIdx.x;
    const int jc0 = j * 8;
    const int tid = threadIdx.x;

    // one-time: Whh slice -> smem, gate-interleaved: Ws[k][cj*4+g]
    {
        int c  = tid >> 3;          // 0..31
        int cj = c >> 2;            // 0..7
        int g  = c & 3;             // gate i/f/g/o
        const float* wr = Whh + (size_t)(g * HDIM + jc0 + cj) * HDIM;
        for (int k0 = (tid & 7) * 4; k0 < HDIM; k0 += 32) {
            float4 w = *(const float4*)(wr + k0);
            Ws[(k0 + 0) * 36 + c] = w.x;
            Ws[(k0 + 1) * 36 + c] = w.y;
            Ws[(k0 + 2) * 36 + c] = w.z;
            Ws[(k0 + 3) * 36 + c] = w.w;
        }
    }

    const int m0    = (tid >> 3) * 2;   // 0..62
    const int cj    = tid & 7;          // h-col within CTA slice
    const int gbase = jc0 + cj;         // column inside each gate block

    // cell state in registers for the whole scan
    float c0r = cbuf[m0 * HDIM + gbase];
    float c1r = cbuf[(m0 + 1) * HDIM + gbase];

    // h staging mapping: row mL, k offset kq within a 32-k chunk
    const int mL = tid >> 2;            // 0..63
    const int kq = (tid & 3) * 8;       // 0,8,16,24

    const float* Hin = Hin0;
    for (int t = 0; t < TSTEPS; t++) {
        const float* Xp   = Xp_base + (size_t)t * (BATCH * G4);
        float*       Hout = Hser    + (size_t)t * (BATCH * HDIM);

        // prefetch Xp early (consumed ~9us later in the activations)
        const float* xr0 = Xp + (size_t)m0 * G4 + gbase;
        const float* xr1 = xr0 + G4;
        float xi0 = xr0[0], xf0 = xr0[1024], xg0 = xr0[2048], xo0 = xr0[3072];
        float xi1 = xr1[0], xf1 = xr1[1024], xg1 = xr1[2048], xo1 = xr1[3072];

        unsigned long long aif0 = 0ull, ago0 = 0ull;   // (i,f),(g,o) row m0
        unsigned long long aif1 = 0ull, ago1 = 0ull;   // row m0+1

        const float* hrow = Hin + mL * HDIM + kq;
        float4 p0 = *(const float4*)(hrow);
        float4 p1 = *(const float4*)(hrow + 4);

        for (int ch = 0; ch < 32; ch++) {
            float* HB = Hd + (ch & 1) * HBUFSZ;
            // stage duplicated h: HB[(kq+i)*HSTR + 2*mL] = (h, h)
            {
                const float v[8] = {p0.x, p0.y, p0.z, p0.w,
                                    p1.x, p1.y, p1.z, p1.w};
#pragma unroll
                for (int i = 0; i < 8; i++)
                    *(float2*)&HB[(kq + i) * HSTR + 2 * mL]
                        = make_float2(v[i], v[i]);
            }
            __syncthreads();
            // (store(ch+2) into this buffer happens only after sync(ch+1),
            //  which follows every thread's compute(ch) -> safe, 1 sync/chunk)
            if (ch < 31) {
                const float* hp = hrow + (ch + 1) * 32;
                p0 = *(const float4*)(hp);
                p1 = *(const float4*)(hp + 4);
            }
            const float* wp  = Ws + (ch * 32) * 36 + cj * 4;
            const float* hq  = HB + 2 * m0;
#pragma unroll
            for (int kc = 0; kc < 32; kc++) {
                unsigned long long h0  = *(const unsigned long long*)(hq + kc * HSTR);
                unsigned long long h1  = *(const unsigned long long*)(hq + kc * HSTR + 2);
                unsigned long long wif = *(const unsigned long long*)(wp + kc * 36);
                unsigned long long wgo = *(const unsigned long long*)(wp + kc * 36 + 2);
                FMA_F32X2(aif0, h0, wif);
                FMA_F32X2(ago0, h0, wgo);
                FMA_F32X2(aif1, h1, wif);
                FMA_F32X2(ago1, h1, wgo);
            }
        }

        // activations fully in registers
        float gi0, gf0, gg0, go0, gi1, gf1, gg1, go1;
        UNPACK_F32X2(gi0, gf0, aif0);
        UNPACK_F32X2(gg0, go0, ago0);
        UNPACK_F32X2(gi1, gf1, aif1);
        UNPACK_F32X2(gg1, go1, ago1);
        gi0 += xi0; gf0 += xf0; gg0 += xg0; go0 += xo0;
        gi1 += xi1; gf1 += xf1; gg1 += xg1; go1 += xo1;

        float ii0 = sigmoidf_fast(gi0), ff0 = sigmoidf_fast(gf0);
        float oo0 = sigmoidf_fast(go0), tg0 = tanhf(gg0);
        float ii1 = sigmoidf_fast(gi1), ff1 = sigmoidf_fast(gf1);
        float oo1 = sigmoidf_fast(go1), tg1 = tanhf(gg1);

        c0r = ff0 * c0r + ii0 * tg0;
        c1r = ff1 * c1r + ii1 * tg1;
        Hout[m0 * HDIM + gbase]       = oo0 * tanhf(c0r);
        Hout[(m0 + 1) * HDIM + gbase] = oo1 * tanhf(c1r);

        grid_barrier();          // publish Hout to all CTAs for step t+1
        Hin = Hout;
    }

    // hand c off (encoder -> decoder seed; decoder's is unused but harmless)
    cbuf[m0 * HDIM + gbase]       = c0r;
    cbuf[(m0 + 1) * HDIM + gbase] = c1r;
}

// ---------------------------------------------------------------------------
extern "C" void kernel_launch(void* const* d_in, const int* in_sizes, int n_in,
                              void* d_out, int out_size)
{
    const float* x      = (const float*)d_in[0]; // [64,512,256]
    const float* W_ih_e = (const float*)d_in[1]; // [4096,256]
    const float* W_hh_e = (const float*)d_in[2]; // [4096,1024]
    const float* b_e    = (const float*)d_in[3]; // [4096]
    const float* W_ih_d = (const float*)d_in[4]; // [4096,1024]
    const float* W_hh_d = (const float*)d_in[5]; // [4096,1024]
    const float* b_d    = (const float*)d_in[6]; // [4096]
    const float* W_out  = (const float*)d_in[7]; // [256,1024]
    const float* b_out  = (const float*)d_in[8]; // [256]
    float* out = (float*)d_out;                  // [64,512,256]

    float *Xe, *Xd, *ench, *dech, *cbuf, *h0;
    cudaGetSymbolAddress((void**)&Xe,   g_Xe);
    cudaGetSymbolAddress((void**)&Xd,   g_Xd);
    cudaGetSymbolAddress((void**)&ench, g_ench);
    cudaGetSymbolAddress((void**)&dech, g_dech);
    cudaGetSymbolAddress((void**)&cbuf, g_c);
    cudaGetSymbolAddress((void**)&h0,   g_h0);

    const int SCAN_SMEM = (36864 + 2 * HBUFSZ) * 4;   // 180736 bytes
    cudaFuncSetAttribute(lstm_scan_kernel,
                         cudaFuncAttributeMaxDynamicSharedMemorySize, SCAN_SMEM);

    // reset h0/c/barrier state (deterministic across graph replays)
    init_state_kernel<<<256, 256>>>();

    // Xe[t,b,:] = x[b,t,:] @ W_ih_e^T + b_e   (m = t*64+b)
    gemm128_kernel<<<dim3(G4 / 128, (TSTEPS * BATCH) / 128), 256>>>(
        x, W_ih_e, b_e, Xe, FDIM, 131072, 256, 4096, 262144);

    // encoder scan (persistent, 512 steps)
    lstm_scan_kernel<<<NCTA_SCAN, 256, SCAN_SMEM>>>(h0, Xe, W_hh_e, cbuf, ench);

    // Xd = enc_hs @ W_ih_d^T + b_d   (enc_hs is [t][b][h])
    gemm128_kernel<<<dim3(G4 / 128, (TSTEPS * BATCH) / 128), 256>>>(
        ench, W_ih_d, b_d, Xd, HDIM, 1024, 65536, 4096, 262144);

    // decoder scan: seeded by enc_hs[511] (= h_T) and cbuf (= c_T)
    lstm_scan_kernel<<<NCTA_SCAN, 256, SCAN_SMEM>>>(
        ench + (size_t)(TSTEPS - 1) * (BATCH * HDIM), Xd, W_hh_d, cbuf, dech);

    // out[b,t,:] = dec_hs[t,b,:] @ W_out^T + b_out
    gemm128_kernel<<<dim3(FDIM / 128, (TSTEPS * BATCH) / 128), 256>>>(
        dech, W_out, b_out, out, HDIM, 1024, 65536, 131072, 256);
}

// round 5
// speedup vs baseline: 1.0011x; 1.0011x over previous
#include <cuda_runtime.h>
#include <math.h>

// ---------------------------------------------------------------------------
// LSTM autoencoder: B=64, T=512, F=256, H=1024
//   init -> gemm(Xe) -> persistent encoder scan -> gemm(Xd)
//        -> persistent decoder scan -> gemm(out)       (6 graph nodes)
// R4: scan inner loop uses fma.rn.f32x2 (packed fp32 FMA, 2x FFMA issue rate),
//     gate-interleaved weights so activations are register-resident, c state
//     lives in registers across all 512 steps, 1 sync per k-chunk.
// ---------------------------------------------------------------------------

#define TSTEPS 512
#define BATCH  64
#define FDIM   256
#define HDIM   1024
#define G4     4096
#define NCTA_SCAN 128

#define HSTR   130          // duplicated-h smem row stride (floats)
#define HBUFSZ (32 * HSTR)  // one 32-k chunk buffer

// Scratch in device globals (no allocation allowed).
__device__ float g_Xe  [134217728]; // [512][64][4096]
__device__ float g_Xd  [134217728]; // [512][64][4096]
__device__ float g_ench[33554432];  // [512][64][1024]
__device__ float g_dech[33554432];  // [512][64][1024]
__device__ float g_c   [BATCH * HDIM];
__device__ float g_h0  [BATCH * HDIM];
__device__ unsigned g_bar_gen;
__device__ unsigned g_bar_cnt;

__global__ void init_state_kernel() {
    int i = blockIdx.x * blockDim.x + threadIdx.x;
    if (i < BATCH * HDIM) { g_c[i] = 0.0f; g_h0[i] = 0.0f; }
    if (i == 0) { g_bar_gen = 0u; g_bar_cnt = 0u; }
}

// packed fp32x2 FMA: acc = a*b + acc (lanewise on 2 floats in a 64-bit reg)
#define FMA_F32X2(acc, a, b) \
    asm("fma.rn.f32x2 %0, %1, %2, %0;" : "+l"(acc) : "l"(a), "l"(b))
#define UNPACK_F32X2(lo, hi, in) \
    asm("mov.b64 {%0, %1}, %2;" : "=f"(lo), "=f"(hi) : "l"(in))

// Sense-reversal grid barrier across the 128 co-resident scan CTAs.
__device__ __forceinline__ void grid_barrier() {
    __syncthreads();
    if (threadIdx.x == 0) {
        unsigned e = *(volatile unsigned*)&g_bar_gen;
        __threadfence();                       // release my CTA's writes
        unsigned a = atomicAdd(&g_bar_cnt, 1u);
        if (a == NCTA_SCAN - 1) {
            atomicExch(&g_bar_cnt, 0u);
            __threadfence();
            *(volatile unsigned*)&g_bar_gen = e + 1u;
        } else {
            while (*(volatile unsigned*)&g_bar_gen == e) { }
            __threadfence();                   // acquire
        }
    }
    __syncthreads();
}

__device__ __forceinline__ float sigmoidf_fast(float x) {
    return 1.0f / (1.0f + __expf(-x));
}

// ---------------------------------------------------------------------------
// fp32 GEMM + bias (unchanged from R3: total gemm time ~35us, not the lever).
// ---------------------------------------------------------------------------
__global__ void __launch_bounds__(256) gemm128_kernel(
    const float* __restrict__ A, const float* __restrict__ W,
    const float* __restrict__ bias, float* __restrict__ C,
    int K, int a_sb, int a_st, int c_sb, int c_st)
{
    __shared__ __align__(16) float As[8][132];
    __shared__ __align__(16) float Bs[8][132];

    const int m0t = blockIdx.y * 128;
    const int n0t = blockIdx.x * 128;
    const int tid = threadIdx.x;
    const int lm  = tid >> 1;
    const int lk  = (tid & 1) * 4;
    const int mb  = (tid >> 4) * 8;
    const int nb  = (tid & 15) * 8;

    const int am = m0t + lm;
    const size_t aoff = (size_t)(am & 63) * a_sb + (size_t)(am >> 6) * a_st;
    const float* arow = A + aoff + lk;
    const float* wrow = W + (size_t)(n0t + lm) * K + lk;

    float acc[8][8] = {};
    float4 av = *(const float4*)(arow);
    float4 bv = *(const float4*)(wrow);

    const int nchunks = K >> 3;
    for (int ch = 0; ch < nchunks; ch++) {
        __syncthreads();
        As[lk + 0][lm] = av.x; As[lk + 1][lm] = av.y;
        As[lk + 2][lm] = av.z; As[lk + 3][lm] = av.w;
        Bs[lk + 0][lm] = bv.x; Bs[lk + 1][lm] = bv.y;
        Bs[lk + 2][lm] = bv.z; Bs[lk + 3][lm] = bv.w;
        __syncthreads();
        if (ch + 1 < nchunks) {
            av = *(const float4*)(arow + (ch + 1) * 8);
            bv = *(const float4*)(wrow + (ch + 1) * 8);
        }
#pragma unroll
        for (int q = 0; q < 8; q++) {
            float4 a0 = *(const float4*)&As[q][mb];
            float4 a1 = *(const float4*)&As[q][mb + 4];
            float4 b0 = *(const float4*)&Bs[q][nb];
            float4 b1 = *(const float4*)&Bs[q][nb + 4];
            float ar[8] = {a0.x, a0.y, a0.z, a0.w, a1.x, a1.y, a1.z, a1.w};
            float br[8] = {b0.x, b0.y, b0.z, b0.w, b1.x, b1.y, b1.z, b1.w};
#pragma unroll
            for (int r = 0; r < 8; r++)
#pragma unroll
                for (int c = 0; c < 8; c++)
                    acc[r][c] += ar[r] * br[c];
        }
    }

    float4 bi0 = *(const float4*)(bias + n0t + nb);
    float4 bi1 = *(const float4*)(bias + n0t + nb + 4);
    const float bb[8] = {bi0.x, bi0.y, bi0.z, bi0.w, bi1.x, bi1.y, bi1.z, bi1.w};

#pragma unroll
    for (int r = 0; r < 8; r++) {
        int m = m0t + mb + r;
        size_t cbase = (size_t)(m & 63) * c_sb + (size_t)(m >> 6) * c_st
                     + n0t + nb;
        float4 o0 = make_float4(acc[r][0] + bb[0], acc[r][1] + bb[1],
                                acc[r][2] + bb[2], acc[r][3] + bb[3]);
        float4 o1 = make_float4(acc[r][4] + bb[4], acc[r][5] + bb[5],
                                acc[r][6] + bb[6], acc[r][7] + bb[7]);
        *(float4*)(C + cbase)     = o0;
        *(float4*)(C + cbase + 4) = o1;
    }
}

// ---------------------------------------------------------------------------
// Persistent LSTM scan, f32x2 edition.
// CTA j (0..127) owns h columns [j*8, j*8+8).
// Thread (tid): rows m0 = (tid>>3)*2 .. +1 ; h-col cj = tid&7.
// It computes the (i,f,g,o) gate quadruple for (row, jc0+cj), accumulated as
// two f32x2 pairs per row: (i,f) and (g,o).
// Whh slice pre-interleaved in smem: Ws[k*36 + cj*4 + gate].
// h chunks staged DUPLICATED in smem: Hd[kc*130 + 2m] = (h, h) so the f32x2
// broadcast operand is one LDS.64, no packing movs in the inner loop.
// Cell state c lives in registers for the whole 512-step scan.
// smem: Ws 147456B + 2 x 32x130 dup-h = 180736B -> 1 CTA/SM.
// ---------------------------------------------------------------------------
__global__ void __launch_bounds__(256) lstm_scan_kernel(
    const float* __restrict__ Hin0,     // [64][1024] initial h
    const float* __restrict__ Xp_base,  // [512][64][4096] input-part (+bias)
    const float* __restrict__ Whh,      // [4096][1024]
    float* __restrict__ cbuf,           // [64][1024] c in/out (seed/handoff)
    float* __restrict__ Hser)           // [512][64][1024] per-step h out
{
    extern __shared__ float sm[];
    float* Ws = sm;                 // [1024][36], col index c = cj*4 + gate
    float* Hd = sm + 36864;         // 2 x HBUFSZ duplicated-h chunk buffers

    const int j   = blockIdx.x;
    const int jc0 = j * 8;
    const int tid = threadIdx.x;

    // one-time: Whh slice -> smem, gate-interleaved: Ws[k][cj*4+g]
    {
        int c  = tid >> 3;          // 0..31
        int cj = c >> 2;            // 0..7
        int g  = c & 3;             // gate i/f/g/o
        const float* wr = Whh + (size_t)(g * HDIM + jc0 + cj) * HDIM;
        for (int k0 = (tid & 7) * 4; k0 < HDIM; k0 += 32) {
            float4 w = *(const float4*)(wr + k0);
            Ws[(k0 + 0) * 36 + c] = w.x;
            Ws[(k0 + 1) * 36 + c] = w.y;
            Ws[(k0 + 2) * 36 + c] = w.z;
            Ws[(k0 + 3) * 36 + c] = w.w;
        }
    }

    const int m0    = (tid >> 3) * 2;   // 0..62
    const int cj    = tid & 7;          // h-col within CTA slice
    const int gbase = jc0 + cj;         // column inside each gate block

    // cell state in registers for the whole scan
    float c0r = cbuf[m0 * HDIM + gbase];
    float c1r = cbuf[(m0 + 1) * HDIM + gbase];

    // h staging mapping: row mL, k offset kq within a 32-k chunk
    const int mL = tid >> 2;            // 0..63
    const int kq = (tid & 3) * 8;       // 0,8,16,24

    const float* Hin = Hin0;
    for (int t = 0; t < TSTEPS; t++) {
        const float* Xp   = Xp_base + (size_t)t * (BATCH * G4);
        float*       Hout = Hser    + (size_t)t * (BATCH * HDIM);

        // prefetch Xp early (consumed ~9us later in the activations)
        const float* xr0 = Xp + (size_t)m0 * G4 + gbase;
        const float* xr1 = xr0 + G4;
        float xi0 = xr0[0], xf0 = xr0[1024], xg0 = xr0[2048], xo0 = xr0[3072];
        float xi1 = xr1[0], xf1 = xr1[1024], xg1 = xr1[2048], xo1 = xr1[3072];

        unsigned long long aif0 = 0ull, ago0 = 0ull;   // (i,f),(g,o) row m0
        unsigned long long aif1 = 0ull, ago1 = 0ull;   // row m0+1

        const float* hrow = Hin + mL * HDIM + kq;
        float4 p0 = *(const float4*)(hrow);
        float4 p1 = *(const float4*)(hrow + 4);

        for (int ch = 0; ch < 32; ch++) {
            float* HB = Hd + (ch & 1) * HBUFSZ;
            // stage duplicated h: HB[(kq+i)*HSTR + 2*mL] = (h, h)
            {
                const float v[8] = {p0.x, p0.y, p0.z, p0.w,
                                    p1.x, p1.y, p1.z, p1.w};
#pragma unroll
                for (int i = 0; i < 8; i++)
                    *(float2*)&HB[(kq + i) * HSTR + 2 * mL]
                        = make_float2(v[i], v[i]);
            }
            __syncthreads();
            // (store(ch+2) into this buffer happens only after sync(ch+1),
            //  which follows every thread's compute(ch) -> safe, 1 sync/chunk)
            if (ch < 31) {
                const float* hp = hrow + (ch + 1) * 32;
                p0 = *(const float4*)(hp);
                p1 = *(const float4*)(hp + 4);
            }
            const float* wp  = Ws + (ch * 32) * 36 + cj * 4;
            const float* hq  = HB + 2 * m0;
#pragma unroll
            for (int kc = 0; kc < 32; kc++) {
                unsigned long long h0  = *(const unsigned long long*)(hq + kc * HSTR);
                unsigned long long h1  = *(const unsigned long long*)(hq + kc * HSTR + 2);
                unsigned long long wif = *(const unsigned long long*)(wp + kc * 36);
                unsigned long long wgo = *(const unsigned long long*)(wp + kc * 36 + 2);
                FMA_F32X2(aif0, h0, wif);
                FMA_F32X2(ago0, h0, wgo);
                FMA_F32X2(aif1, h1, wif);
                FMA_F32X2(ago1, h1, wgo);
            }
        }

        // activations fully in registers
        float gi0, gf0, gg0, go0, gi1, gf1, gg1, go1;
        UNPACK_F32X2(gi0, gf0, aif0);
        UNPACK_F32X2(gg0, go0, ago0);
        UNPACK_F32X2(gi1, gf1, aif1);
        UNPACK_F32X2(gg1, go1, ago1);
        gi0 += xi0; gf0 += xf0; gg0 += xg0; go0 += xo0;
        gi1 += xi1; gf1 += xf1; gg1 += xg1; go1 += xo1;

        float ii0 = sigmoidf_fast(gi0), ff0 = sigmoidf_fast(gf0);
        float oo0 = sigmoidf_fast(go0), tg0 = tanhf(gg0);
        float ii1 = sigmoidf_fast(gi1), ff1 = sigmoidf_fast(gf1);
        float oo1 = sigmoidf_fast(go1), tg1 = tanhf(gg1);

        c0r = ff0 * c0r + ii0 * tg0;
        c1r = ff1 * c1r + ii1 * tg1;
        Hout[m0 * HDIM + gbase]       = oo0 * tanhf(c0r);
        Hout[(m0 + 1) * HDIM + gbase] = oo1 * tanhf(c1r);

        grid_barrier();          // publish Hout to all CTAs for step t+1
        Hin = Hout;
    }

    // hand c off (encoder -> decoder seed; decoder's is unused but harmless)
    cbuf[m0 * HDIM + gbase]       = c0r;
    cbuf[(m0 + 1) * HDIM + gbase] = c1r;
}

// ---------------------------------------------------------------------------
extern "C" void kernel_launch(void* const* d_in, const int* in_sizes, int n_in,
                              void* d_out, int out_size)
{
    const float* x      = (const float*)d_in[0]; // [64,512,256]
    const float* W_ih_e = (const float*)d_in[1]; // [4096,256]
    const float* W_hh_e = (const float*)d_in[2]; // [4096,1024]
    const float* b_e    = (const float*)d_in[3]; // [4096]
    const float* W_ih_d = (const float*)d_in[4]; // [4096,1024]
    const float* W_hh_d = (const float*)d_in[5]; // [4096,1024]
    const float* b_d    = (const float*)d_in[6]; // [4096]
    const float* W_out  = (const float*)d_in[7]; // [256,1024]
    const float* b_out  = (const float*)d_in[8]; // [256]
    float* out = (float*)d_out;                  // [64,512,256]

    float *Xe, *Xd, *ench, *dech, *cbuf, *h0;
    cudaGetSymbolAddress((void**)&Xe,   g_Xe);
    cudaGetSymbolAddress((void**)&Xd,   g_Xd);
    cudaGetSymbolAddress((void**)&ench, g_ench);
    cudaGetSymbolAddress((void**)&dech, g_dech);
    cudaGetSymbolAddress((void**)&cbuf, g_c);
    cudaGetSymbolAddress((void**)&h0,   g_h0);

    const int SCAN_SMEM = (36864 + 2 * HBUFSZ) * 4;   // 180736 bytes
    cudaFuncSetAttribute(lstm_scan_kernel,
                         cudaFuncAttributeMaxDynamicSharedMemorySize, SCAN_SMEM);

    // reset h0/c/barrier state (deterministic across graph replays)
    init_state_kernel<<<256, 256>>>();

    // Xe[t,b,:] = x[b,t,:] @ W_ih_e^T + b_e   (m = t*64+b)
    gemm128_kernel<<<dim3(G4 / 128, (TSTEPS * BATCH) / 128), 256>>>(
        x, W_ih_e, b_e, Xe, FDIM, 131072, 256, 4096, 262144);

    // encoder scan (persistent, 512 steps)
    lstm_scan_kernel<<<NCTA_SCAN, 256, SCAN_SMEM>>>(h0, Xe, W_hh_e, cbuf, ench);

    // Xd = enc_hs @ W_ih_d^T + b_d   (enc_hs is [t][b][h])
    gemm128_kernel<<<dim3(G4 / 128, (TSTEPS * BATCH) / 128), 256>>>(
        ench, W_ih_d, b_d, Xd, HDIM, 1024, 65536, 4096, 262144);

    // decoder scan: seeded by enc_hs[511] (= h_T) and cbuf (= c_T)
    lstm_scan_kernel<<<NCTA_SCAN, 256, SCAN_SMEM>>>(
        ench + (size_t)(TSTEPS - 1) * (BATCH * HDIM), Xd, W_hh_d, cbuf, dech);

    // out[b,t,:] = dec_hs[t,b,:] @ W_out^T + b_out
    gemm128_kernel<<<dim3(FDIM / 128, (TSTEPS * BATCH) / 128), 256>>>(
        dech, W_out, b_out, out, HDIM, 1024, 65536, 131072, 256);
}

// round 6
// speedup vs baseline: 1.3787x; 1.3773x over previous
#include <cuda_runtime.h>
#include <math.h>
#include <stdint.h>

// ---------------------------------------------------------------------------
// LSTM autoencoder: B=64, T=512, F=256, H=1024
//   init -> gemm(Xe) -> persistent encoder scan -> gemm(Xd)
//        -> persistent decoder scan -> gemm(out)       (6 graph nodes)
// R5: scalar-FFMA scan (R4's f32x2 regressed) + cp.async depth-4 pipeline for
//     the per-chunk h staging (the verified R3/R4 bottleneck: exposed L2
//     latency with only 2 warps/SMSP). No-transpose [m][k] h tiles,
//     gate-interleaved weights, register-resident activations & cell state.
// ---------------------------------------------------------------------------

#define TSTEPS 512
#define BATCH  64
#define FDIM   256
#define HDIM   1024
#define G4     4096
#define NCTA_SCAN 128

#define HP     36            // h tile row stride (floats), pad vs 32 banks
#define HTILE  (64 * HP)     // floats per chunk buffer (2304)
#define NBUF   4             // pipeline depth

// Scratch in device globals (no allocation allowed).
__device__ float g_Xe  [134217728]; // [512][64][4096]
__device__ float g_Xd  [134217728]; // [512][64][4096]
__device__ float g_ench[33554432];  // [512][64][1024]
__device__ float g_dech[33554432];  // [512][64][1024]
__device__ float g_c   [BATCH * HDIM];
__device__ float g_h0  [BATCH * HDIM];
__device__ unsigned g_bar_gen;
__device__ unsigned g_bar_cnt;

__global__ void init_state_kernel() {
    int i = blockIdx.x * blockDim.x + threadIdx.x;
    if (i < BATCH * HDIM) { g_c[i] = 0.0f; g_h0[i] = 0.0f; }
    if (i == 0) { g_bar_gen = 0u; g_bar_cnt = 0u; }
}

// Sense-reversal grid barrier across the 128 co-resident scan CTAs.
__device__ __forceinline__ void grid_barrier() {
    __syncthreads();
    if (threadIdx.x == 0) {
        unsigned e = *(volatile unsigned*)&g_bar_gen;
        __threadfence();                       // release my CTA's writes
        unsigned a = atomicAdd(&g_bar_cnt, 1u);
        if (a == NCTA_SCAN - 1) {
            atomicExch(&g_bar_cnt, 0u);
            __threadfence();
            *(volatile unsigned*)&g_bar_gen = e + 1u;
        } else {
            while (*(volatile unsigned*)&g_bar_gen == e) { }
            __threadfence();                   // acquire
        }
    }
    __syncthreads();
}

__device__ __forceinline__ float sigmoidf_fast(float x) {
    return 1.0f / (1.0f + __expf(-x));
}

__device__ __forceinline__ void cp16(uint32_t dst, const float* src) {
    asm volatile("cp.async.cg.shared.global [%0], [%1], 16;"
                 :: "r"(dst), "l"(src));
}
__device__ __forceinline__ void cp_commit() {
    asm volatile("cp.async.commit_group;");
}
__device__ __forceinline__ void cp_wait2() {
    asm volatile("cp.async.wait_group 2;");
}
__device__ __forceinline__ void cp_wait0() {
    asm volatile("cp.async.wait_group 0;");
}

// ---------------------------------------------------------------------------
// fp32 GEMM + bias (total gemm time ~35us; not the lever).
// ---------------------------------------------------------------------------
__global__ void __launch_bounds__(256) gemm128_kernel(
    const float* __restrict__ A, const float* __restrict__ W,
    const float* __restrict__ bias, float* __restrict__ C,
    int K, int a_sb, int a_st, int c_sb, int c_st)
{
    __shared__ __align__(16) float As[8][132];
    __shared__ __align__(16) float Bs[8][132];

    const int m0t = blockIdx.y * 128;
    const int n0t = blockIdx.x * 128;
    const int tid = threadIdx.x;
    const int lm  = tid >> 1;
    const int lk  = (tid & 1) * 4;
    const int mb  = (tid >> 4) * 8;
    const int nb  = (tid & 15) * 8;

    const int am = m0t + lm;
    const size_t aoff = (size_t)(am & 63) * a_sb + (size_t)(am >> 6) * a_st;
    const float* arow = A + aoff + lk;
    const float* wrow = W + (size_t)(n0t + lm) * K + lk;

    float acc[8][8] = {};
    float4 av = *(const float4*)(arow);
    float4 bv = *(const float4*)(wrow);

    const int nchunks = K >> 3;
    for (int ch = 0; ch < nchunks; ch++) {
        __syncthreads();
        As[lk + 0][lm] = av.x; As[lk + 1][lm] = av.y;
        As[lk + 2][lm] = av.z; As[lk + 3][lm] = av.w;
        Bs[lk + 0][lm] = bv.x; Bs[lk + 1][lm] = bv.y;
        Bs[lk + 2][lm] = bv.z; Bs[lk + 3][lm] = bv.w;
        __syncthreads();
        if (ch + 1 < nchunks) {
            av = *(const float4*)(arow + (ch + 1) * 8);
            bv = *(const float4*)(wrow + (ch + 1) * 8);
        }
#pragma unroll
        for (int q = 0; q < 8; q++) {
            float4 a0 = *(const float4*)&As[q][mb];
            float4 a1 = *(const float4*)&As[q][mb + 4];
            float4 b0 = *(const float4*)&Bs[q][nb];
            float4 b1 = *(const float4*)&Bs[q][nb + 4];
            float ar[8] = {a0.x, a0.y, a0.z, a0.w, a1.x, a1.y, a1.z, a1.w};
            float br[8] = {b0.x, b0.y, b0.z, b0.w, b1.x, b1.y, b1.z, b1.w};
#pragma unroll
            for (int r = 0; r < 8; r++)
#pragma unroll
                for (int c = 0; c < 8; c++)
                    acc[r][c] += ar[r] * br[c];
        }
    }

    float4 bi0 = *(const float4*)(bias + n0t + nb);
    float4 bi1 = *(const float4*)(bias + n0t + nb + 4);
    const float bb[8] = {bi0.x, bi0.y, bi0.z, bi0.w, bi1.x, bi1.y, bi1.z, bi1.w};

#pragma unroll
    for (int r = 0; r < 8; r++) {
        int m = m0t + mb + r;
        size_t cbase = (size_t)(m & 63) * c_sb + (size_t)(m >> 6) * c_st
                     + n0t + nb;
        float4 o0 = make_float4(acc[r][0] + bb[0], acc[r][1] + bb[1],
                                acc[r][2] + bb[2], acc[r][3] + bb[3]);
        float4 o1 = make_float4(acc[r][4] + bb[4], acc[r][5] + bb[5],
                                acc[r][6] + bb[6], acc[r][7] + bb[7]);
        *(float4*)(C + cbase)     = o0;
        *(float4*)(C + cbase + 4) = o1;
    }
}

// ---------------------------------------------------------------------------
// Persistent LSTM scan, cp.async edition.
// CTA j owns h cols [j*8, j*8+8). Thread: rows m0, m0+1 ; h-col cj = tid&7.
// Weights gate-interleaved in smem: Ws[k*36 + cj*4 + gate] -> one LDS.128
// yields (i,f,g,o) weights for column cj at this k.
// h chunks (32 k) staged untransposed [m][k] via cp.async, 4-deep ring.
// Activations & cell state fully register-resident.
// smem: Ws 147456B + 4 x 64x36 h tiles 36864B = 184320B -> 1 CTA/SM.
// ---------------------------------------------------------------------------
__global__ void __launch_bounds__(256) lstm_scan_kernel(
    const float* __restrict__ Hin0,     // [64][1024] initial h
    const float* __restrict__ Xp_base,  // [512][64][4096] input-part (+bias)
    const float* __restrict__ Whh,      // [4096][1024]
    float* __restrict__ cbuf,           // [64][1024] c seed in / c_T out
    float* __restrict__ Hser)           // [512][64][1024] per-step h out
{
    extern __shared__ float sm[];
    float* Ws = sm;                     // [1024][36]
    float* Hs = sm + 36864;             // NBUF x HTILE

    const int j   = blockIdx.x;
    const int jc0 = j * 8;
    const int tid = threadIdx.x;

    const uint32_t hs_u32 =
        (uint32_t)__cvta_generic_to_shared(Hs);

    // one-time: Whh slice -> smem, gate-interleaved: Ws[k][cj*4+gate]
    {
        int c  = tid >> 3;              // 0..31
        int cj = c >> 2;                // 0..7
        int g  = c & 3;                 // i/f/g/o
        const float* wr = Whh + (size_t)(g * HDIM + jc0 + cj) * HDIM;
        for (int k0 = (tid & 7) * 4; k0 < HDIM; k0 += 32) {
            float4 w = *(const float4*)(wr + k0);
            Ws[(k0 + 0) * 36 + c] = w.x;
            Ws[(k0 + 1) * 36 + c] = w.y;
            Ws[(k0 + 2) * 36 + c] = w.z;
            Ws[(k0 + 3) * 36 + c] = w.w;
        }
    }

    const int m0    = (tid >> 3) * 2;   // 0..62
    const int cj    = tid & 7;
    const int gbase = jc0 + cj;

    // per-thread copy assignment: 2 x 16B segments (512 segs = 64 rows x 8)
    const int r0 = (tid * 2)     >> 3;
    const int s0 = (tid * 2)      & 7;
    const int r1 = (tid * 2 + 1) >> 3;
    const int s1 = (tid * 2 + 1)  & 7;

    // cell state in registers for the whole scan
    float c0r = cbuf[m0 * HDIM + gbase];
    float c1r = cbuf[(m0 + 1) * HDIM + gbase];

    const float* Hin = Hin0;
    for (int t = 0; t < TSTEPS; t++) {
        const float* Xp   = Xp_base + (size_t)t * (BATCH * G4);
        float*       Hout = Hser    + (size_t)t * (BATCH * HDIM);

        // prefetch Xp early (consumed ~17us later)
        const float* xr0 = Xp + (size_t)m0 * G4 + gbase;
        const float* xr1 = xr0 + G4;
        float xi0 = xr0[0], xf0 = xr0[1024], xg0 = xr0[2048], xo0 = xr0[3072];
        float xi1 = xr1[0], xf1 = xr1[1024], xg1 = xr1[2048], xo1 = xr1[3072];

        // prologue: issue chunks 0..2
#pragma unroll
        for (int p = 0; p < 3; p++) {
            uint32_t hb = hs_u32 + (uint32_t)((p & 3) * HTILE) * 4u;
            cp16(hb + (uint32_t)(r0 * HP + s0 * 4) * 4u,
                 Hin + r0 * HDIM + p * 32 + s0 * 4);
            cp16(hb + (uint32_t)(r1 * HP + s1 * 4) * 4u,
                 Hin + r1 * HDIM + p * 32 + s1 * 4);
            cp_commit();
        }

        float a00 = 0.f, a01 = 0.f, a02 = 0.f, a03 = 0.f;
        float a10 = 0.f, a11 = 0.f, a12 = 0.f, a13 = 0.f;

        for (int ch = 0; ch < 32; ch++) {
            cp_wait2();                  // chunk ch complete (this thread)
            __syncthreads();             // ... and every thread's parts
            {                            // issue chunk ch+3 (or empty group)
                int nc = ch + 3;
                if (nc < 32) {
                    uint32_t hb = hs_u32 + (uint32_t)((nc & 3) * HTILE) * 4u;
                    cp16(hb + (uint32_t)(r0 * HP + s0 * 4) * 4u,
                         Hin + r0 * HDIM + nc * 32 + s0 * 4);
                    cp16(hb + (uint32_t)(r1 * HP + s1 * 4) * 4u,
                         Hin + r1 * HDIM + nc * 32 + s1 * 4);
                }
                cp_commit();             // empty groups keep wait_group<2> valid
            }

            const float* hb = Hs + (ch & 3) * HTILE + m0 * HP;
            const float* wp = Ws + (ch * 32) * 36 + cj * 4;
#pragma unroll
            for (int kc = 0; kc < 32; kc++) {
                float  h0 = hb[kc];
                float  h1 = hb[HP + kc];
                float4 w  = *(const float4*)(wp + kc * 36);
                a00 += h0 * w.x; a01 += h0 * w.y;
                a02 += h0 * w.z; a03 += h0 * w.w;
                a10 += h1 * w.x; a11 += h1 * w.y;
                a12 += h1 * w.z; a13 += h1 * w.w;
            }
        }
        cp_wait0();                      // drain empty groups before reuse

        // activations fully in registers  (a0: i,f,g,o for row m0; a1: m0+1)
        float gi0 = a00 + xi0, gf0 = a01 + xf0;
        float gg0 = a02 + xg0, go0 = a03 + xo0;
        float gi1 = a10 + xi1, gf1 = a11 + xf1;
        float gg1 = a12 + xg1, go1 = a13 + xo1;

        float ii0 = sigmoidf_fast(gi0), ff0 = sigmoidf_fast(gf0);
        float oo0 = sigmoidf_fast(go0), tg0 = tanhf(gg0);
        float ii1 = sigmoidf_fast(gi1), ff1 = sigmoidf_fast(gf1);
        float oo1 = sigmoidf_fast(go1), tg1 = tanhf(gg1);

        c0r = ff0 * c0r + ii0 * tg0;
        c1r = ff1 * c1r + ii1 * tg1;
        Hout[m0 * HDIM + gbase]       = oo0 * tanhf(c0r);
        Hout[(m0 + 1) * HDIM + gbase] = oo1 * tanhf(c1r);

        grid_barrier();                  // publish Hout for step t+1
        Hin = Hout;
    }

    // hand c off (encoder c_T seeds the decoder)
    cbuf[m0 * HDIM + gbase]       = c0r;
    cbuf[(m0 + 1) * HDIM + gbase] = c1r;
}

// ---------------------------------------------------------------------------
extern "C" void kernel_launch(void* const* d_in, const int* in_sizes, int n_in,
                              void* d_out, int out_size)
{
    const float* x      = (const float*)d_in[0]; // [64,512,256]
    const float* W_ih_e = (const float*)d_in[1]; // [4096,256]
    const float* W_hh_e = (const float*)d_in[2]; // [4096,1024]
    const float* b_e    = (const float*)d_in[3]; // [4096]
    const float* W_ih_d = (const float*)d_in[4]; // [4096,1024]
    const float* W_hh_d = (const float*)d_in[5]; // [4096,1024]
    const float* b_d    = (const float*)d_in[6]; // [4096]
    const float* W_out  = (const float*)d_in[7]; // [256,1024]
    const float* b_out  = (const float*)d_in[8]; // [256]
    float* out = (float*)d_out;                  // [64,512,256]

    float *Xe, *Xd, *ench, *dech, *cbuf, *h0;
    cudaGetSymbolAddress((void**)&Xe,   g_Xe);
    cudaGetSymbolAddress((void**)&Xd,   g_Xd);
    cudaGetSymbolAddress((void**)&ench, g_ench);
    cudaGetSymbolAddress((void**)&dech, g_dech);
    cudaGetSymbolAddress((void**)&cbuf, g_c);
    cudaGetSymbolAddress((void**)&h0,   g_h0);

    const int SCAN_SMEM = (36864 + NBUF * HTILE) * 4;   // 184320 bytes
    cudaFuncSetAttribute(lstm_scan_kernel,
                         cudaFuncAttributeMaxDynamicSharedMemorySize, SCAN_SMEM);

    // reset h0/c/barrier state (deterministic across graph replays)
    init_state_kernel<<<256, 256>>>();

    // Xe[t,b,:] = x[b,t,:] @ W_ih_e^T + b_e   (m = t*64+b)
    gemm128_kernel<<<dim3(G4 / 128, (TSTEPS * BATCH) / 128), 256>>>(
        x, W_ih_e, b_e, Xe, FDIM, 131072, 256, 4096, 262144);

    // encoder scan (persistent, 512 steps)
    lstm_scan_kernel<<<NCTA_SCAN, 256, SCAN_SMEM>>>(h0, Xe, W_hh_e, cbuf, ench);

    // Xd = enc_hs @ W_ih_d^T + b_d   (enc_hs is [t][b][h])
    gemm128_kernel<<<dim3(G4 / 128, (TSTEPS * BATCH) / 128), 256>>>(
        ench, W_ih_d, b_d, Xd, HDIM, 1024, 65536, 4096, 262144);

    // decoder scan: seeded by enc_hs[511] (= h_T) and cbuf (= c_T)
    lstm_scan_kernel<<<NCTA_SCAN, 256, SCAN_SMEM>>>(
        ench + (size_t)(TSTEPS - 1) * (BATCH * HDIM), Xd, W_hh_d, cbuf, dech);

    // out[b,t,:] = dec_hs[t,b,:] @ W_out^T + b_out
    gemm128_kernel<<<dim3(FDIM / 128, (TSTEPS * BATCH) / 128), 256>>>(
        dech, W_out, b_out, out, HDIM, 1024, 65536, 131072, 256);
}